// round 1
// baseline (speedup 1.0000x reference)
#include <cuda_runtime.h>
#include <math.h>

#define BB 64
#define LL 512
#define DD 768

// Scratch (device globals: allocation-free per harness rules)
__device__ float g_E[(size_t)BB * LL * LL];   // exp(att), 64 MB
__device__ float g_invp[BB * LL];             // 1/max(||p_i||, eps)
__device__ float g_invq[BB * LL];
__device__ float g_rinv[BB * LL];             // 1/rowsum of E
__device__ float g_cinv[BB * LL];             // 1/colsum of E

// ---------------------------------------------------------------------------
// Kernel 1: inverse L2 norms of rows of p and q. One warp per row.
// ---------------------------------------------------------------------------
__global__ void norms_kernel(const float* __restrict__ p,
                             const float* __restrict__ q) {
    int warp = (blockIdx.x * blockDim.x + threadIdx.x) >> 5;
    int lane = threadIdx.x & 31;
    if (warp >= 2 * BB * LL) return;
    const float* src;
    float* dst;
    int r;
    if (warp < BB * LL) { src = p; dst = g_invp; r = warp; }
    else                { src = q; dst = g_invq; r = warp - BB * LL; }
    const float4* row = (const float4*)(src + (size_t)r * DD);
    float s = 0.f;
#pragma unroll
    for (int i = 0; i < DD / 4 / 32; i++) {   // 6
        float4 v = row[lane + i * 32];
        s += v.x * v.x + v.y * v.y + v.z * v.z + v.w * v.w;
    }
#pragma unroll
    for (int o = 16; o; o >>= 1) s += __shfl_xor_sync(0xffffffffu, s, o);
    if (lane == 0) dst[r] = 1.f / fmaxf(sqrtf(s), 1e-8f);
}

// ---------------------------------------------------------------------------
// Kernel 2: E[b,i,j] = exp( (p_i . q_j) * invp[i] * invq[j] )
// NT SGEMM: A=p[b] [512x768] row-major, B=q[b] [512x768] row-major.
// 128x128 block tile, BK=8, 256 threads, 8x8 microtile (4+4 split).
// ---------------------------------------------------------------------------
__global__ __launch_bounds__(256)
void att_kernel(const float* __restrict__ P, const float* __restrict__ Q) {
    int b = blockIdx.z;
    const float* A = P + (size_t)b * LL * DD;
    const float* B = Q + (size_t)b * LL * DD;
    float* Eb = g_E + (size_t)b * LL * LL;
    const float* ip = g_invp + b * LL;
    const float* iq = g_invq + b * LL;
    int m0 = blockIdx.y * 128, n0 = blockIdx.x * 128;

    __shared__ float As[8][128];
    __shared__ float Bs[8][128];

    int t = threadIdx.x;
    int lm = t >> 1, lk = (t & 1) * 4;   // global-load mapping
    int tx = t & 15, ty = t >> 4;        // compute mapping

    float acc[8][8];
#pragma unroll
    for (int i = 0; i < 8; i++)
#pragma unroll
        for (int j = 0; j < 8; j++) acc[i][j] = 0.f;

    const float* aptr = A + (size_t)(m0 + lm) * DD + lk;
    const float* bptr = B + (size_t)(n0 + lm) * DD + lk;

    for (int k0 = 0; k0 < DD; k0 += 8) {
        float4 av = *(const float4*)(aptr + k0);
        float4 bv = *(const float4*)(bptr + k0);
        __syncthreads();
        As[lk + 0][lm] = av.x; As[lk + 1][lm] = av.y;
        As[lk + 2][lm] = av.z; As[lk + 3][lm] = av.w;
        Bs[lk + 0][lm] = bv.x; Bs[lk + 1][lm] = bv.y;
        Bs[lk + 2][lm] = bv.z; Bs[lk + 3][lm] = bv.w;
        __syncthreads();
#pragma unroll
        for (int kk = 0; kk < 8; kk++) {
            float a[8], bb[8];
            *(float4*)&a[0]  = *(const float4*)&As[kk][ty * 4];
            *(float4*)&a[4]  = *(const float4*)&As[kk][64 + ty * 4];
            *(float4*)&bb[0] = *(const float4*)&Bs[kk][tx * 4];
            *(float4*)&bb[4] = *(const float4*)&Bs[kk][64 + tx * 4];
#pragma unroll
            for (int i = 0; i < 8; i++)
#pragma unroll
                for (int j = 0; j < 8; j++) acc[i][j] += a[i] * bb[j];
        }
    }

    // epilogue: scale to cosine, exp, store E (float4)
#pragma unroll
    for (int i = 0; i < 8; i++) {
        int m = m0 + ty * 4 + (i & 3) + (i >> 2) * 64;
        float rp = ip[m];
#pragma unroll
        for (int jg = 0; jg < 2; jg++) {
            int nb = n0 + tx * 4 + jg * 64;
            float4 v;
            v.x = __expf(acc[i][jg * 4 + 0] * rp * iq[nb + 0]);
            v.y = __expf(acc[i][jg * 4 + 1] * rp * iq[nb + 1]);
            v.z = __expf(acc[i][jg * 4 + 2] * rp * iq[nb + 2]);
            v.w = __expf(acc[i][jg * 4 + 3] * rp * iq[nb + 3]);
            *(float4*)&Eb[(size_t)m * LL + nb] = v;
        }
    }
}

// ---------------------------------------------------------------------------
// Kernel 3a: rowsum of E -> g_rinv. One warp per row (512 elems).
// ---------------------------------------------------------------------------
__global__ void rowsum_kernel() {
    int warp = (blockIdx.x * blockDim.x + threadIdx.x) >> 5;
    int lane = threadIdx.x & 31;
    if (warp >= BB * LL) return;
    const float4* row = (const float4*)(g_E + (size_t)warp * LL);
    float s = 0.f;
#pragma unroll
    for (int i = 0; i < 4; i++) {
        float4 v = row[lane + i * 32];
        s += v.x + v.y + v.z + v.w;
    }
#pragma unroll
    for (int o = 16; o; o >>= 1) s += __shfl_xor_sync(0xffffffffu, s, o);
    if (lane == 0) g_rinv[warp] = 1.f / s;
}

// ---------------------------------------------------------------------------
// Kernel 3b: colsum of E -> g_cinv. One block per batch, thread per column.
// ---------------------------------------------------------------------------
__global__ void colsum_kernel() {
    int b = blockIdx.x;
    int j = threadIdx.x;          // 512 threads
    const float* Eb = g_E + (size_t)b * LL * LL;
    float s0 = 0.f, s1 = 0.f, s2 = 0.f, s3 = 0.f;
    for (int i = 0; i < LL; i += 4) {
        s0 += Eb[(size_t)(i + 0) * LL + j];
        s1 += Eb[(size_t)(i + 1) * LL + j];
        s2 += Eb[(size_t)(i + 2) * LL + j];
        s3 += Eb[(size_t)(i + 3) * LL + j];
    }
    g_cinv[b * LL + j] = 1.f / (s0 + s1 + s2 + s3);
}

// ---------------------------------------------------------------------------
// Kernel 4: NN SGEMM with optional row/col scaling.
// MODE 0 (out_p): C[m,n] = rinv[m] * sum_k E[m,k] * V[k,n],   V = q
// MODE 1 (out_q): C[m,n] =           sum_k (cinv[k]*E[m,k]) * V[k,n], V = p
// M=512 (m), N=768 (d), K=512 (k). Same 128x128x8 tile scheme.
// ---------------------------------------------------------------------------
template <int MODE>
__global__ __launch_bounds__(256)
void out_kernel(const float* __restrict__ V, float* __restrict__ Out) {
    int b = blockIdx.z;
    const float* A = g_E + (size_t)b * LL * LL;        // [512 x 512]
    const float* Bv = V + (size_t)b * LL * DD;         // [512 x 768]
    float* Cb = Out + (size_t)b * LL * DD;
    int m0 = blockIdx.y * 128, n0 = blockIdx.x * 128;

    __shared__ float As[8][128];
    __shared__ float Bs[8][128];

    int t = threadIdx.x;
    int lm = t >> 1, lk = (t & 1) * 4;   // A tile mapping: row lm, cols lk..lk+3
    int bk = t >> 5, bn = (t & 31) * 4;  // B tile mapping: row bk, cols bn..bn+3
    int tx = t & 15, ty = t >> 4;

    float acc[8][8];
#pragma unroll
    for (int i = 0; i < 8; i++)
#pragma unroll
        for (int j = 0; j < 8; j++) acc[i][j] = 0.f;

    for (int k0 = 0; k0 < LL; k0 += 8) {
        float4 av = *(const float4*)(A + (size_t)(m0 + lm) * LL + k0 + lk);
        if (MODE == 1) {
            float4 cs = *(const float4*)&g_cinv[b * LL + k0 + lk];
            av.x *= cs.x; av.y *= cs.y; av.z *= cs.z; av.w *= cs.w;
        }
        float4 bv = *(const float4*)(Bv + (size_t)(k0 + bk) * DD + n0 + bn);
        __syncthreads();
        As[lk + 0][lm] = av.x; As[lk + 1][lm] = av.y;
        As[lk + 2][lm] = av.z; As[lk + 3][lm] = av.w;
        *(float4*)&Bs[bk][bn] = bv;
        __syncthreads();
#pragma unroll
        for (int kk = 0; kk < 8; kk++) {
            float a[8], bb[8];
            *(float4*)&a[0]  = *(const float4*)&As[kk][ty * 4];
            *(float4*)&a[4]  = *(const float4*)&As[kk][64 + ty * 4];
            *(float4*)&bb[0] = *(const float4*)&Bs[kk][tx * 4];
            *(float4*)&bb[4] = *(const float4*)&Bs[kk][64 + tx * 4];
#pragma unroll
            for (int i = 0; i < 8; i++)
#pragma unroll
                for (int j = 0; j < 8; j++) acc[i][j] += a[i] * bb[j];
        }
    }

#pragma unroll
    for (int i = 0; i < 8; i++) {
        int m = m0 + ty * 4 + (i & 3) + (i >> 2) * 64;
        float rs = (MODE == 0) ? g_rinv[b * LL + m] : 1.f;
#pragma unroll
        for (int jg = 0; jg < 2; jg++) {
            int nb = n0 + tx * 4 + jg * 64;
            float4 v;
            v.x = acc[i][jg * 4 + 0] * rs;
            v.y = acc[i][jg * 4 + 1] * rs;
            v.z = acc[i][jg * 4 + 2] * rs;
            v.w = acc[i][jg * 4 + 3] * rs;
            *(float4*)&Cb[(size_t)m * DD + nb] = v;
        }
    }
}

// ---------------------------------------------------------------------------
extern "C" void kernel_launch(void* const* d_in, const int* in_sizes, int n_in,
                              void* d_out, int out_size) {
    const float* p = (const float*)d_in[0];
    const float* q = (const float*)d_in[1];
    float* out = (float*)d_out;
    float* out_p = out;
    float* out_q = out + (size_t)BB * LL * DD;

    norms_kernel<<<(2 * BB * LL) / 8, 256>>>(p, q);

    dim3 g_att(LL / 128, LL / 128, BB);       // (4,4,64)
    att_kernel<<<g_att, 256>>>(p, q);

    rowsum_kernel<<<(BB * LL) / 8, 256>>>();
    colsum_kernel<<<BB, LL>>>();

    dim3 g_out(DD / 128, LL / 128, BB);       // (6,4,64)
    out_kernel<0><<<g_out, 256>>>(q, out_p);
    out_kernel<1><<<g_out, 256>>>(p, out_q);
}

// round 5
// speedup vs baseline: 1.1435x; 1.1435x over previous
#include <cuda_runtime.h>
#include <cuda_bf16.h>
#include <cstdint>
#include <math.h>

#define BB 64
#define LL 512
#define DD 768

// ---------------------------------------------------------------------------
// Scratch (device globals)
// ---------------------------------------------------------------------------
__device__ float g_E[(size_t)BB * LL * LL];   // exp(att), fp32, 67 MB
__device__ float g_invp[BB * LL];
__device__ float g_invq[BB * LL];
__device__ float g_rinv[BB * LL];
__device__ float g_cinv[BB * LL];

// ---------------------------------------------------------------------------
// Helpers
// ---------------------------------------------------------------------------
__device__ __forceinline__ uint32_t smem_u32(const void* p) {
    uint32_t a;
    asm("{ .reg .u64 t; cvta.to.shared.u64 t, %1; cvt.u32.u64 %0, t; }"
        : "=r"(a) : "l"(p));
    return a;
}
#define CP_ASYNC(dst, src) \
    asm volatile("cp.async.cg.shared.global [%0], [%1], 16;" :: "r"(dst), "l"(src))
#define CP_COMMIT() asm volatile("cp.async.commit_group;")
#define CP_WAIT1()  asm volatile("cp.async.wait_group 1;")
#define CP_WAIT0()  asm volatile("cp.async.wait_group 0;")

__device__ __forceinline__ void mma16816(float* c, const uint32_t* a, const uint32_t* b) {
    asm volatile("mma.sync.aligned.m16n8k16.row.col.f32.bf16.bf16.f32 "
                 "{%0,%1,%2,%3}, {%4,%5,%6,%7}, {%8,%9}, {%0,%1,%2,%3};"
                 : "+f"(c[0]), "+f"(c[1]), "+f"(c[2]), "+f"(c[3])
                 : "r"(a[0]), "r"(a[1]), "r"(a[2]), "r"(a[3]), "r"(b[0]), "r"(b[1]));
}
// split a float2 into packed bf16x2 hi and lo (x -> low 16 bits)
__device__ __forceinline__ void splitp(float2 v, uint32_t& hi, uint32_t& lo) {
    __nv_bfloat162 h = __floats2bfloat162_rn(v.x, v.y);
    hi = *(uint32_t*)&h;
    float hx = __bfloat162float(h.x);
    float hy = __bfloat162float(h.y);
    __nv_bfloat162 l = __floats2bfloat162_rn(v.x - hx, v.y - hy);
    lo = *(uint32_t*)&l;
}

// ---------------------------------------------------------------------------
// inverse L2 norms (proven R1)
// ---------------------------------------------------------------------------
__global__ void norms_kernel(const float* __restrict__ p,
                             const float* __restrict__ q) {
    int warp = (blockIdx.x * blockDim.x + threadIdx.x) >> 5;
    int lane = threadIdx.x & 31;
    if (warp >= 2 * BB * LL) return;
    const float* src; float* dst; int r;
    if (warp < BB * LL) { src = p; dst = g_invp; r = warp; }
    else                { src = q; dst = g_invq; r = warp - BB * LL; }
    const float4* row = (const float4*)(src + (size_t)r * DD);
    float s = 0.f;
#pragma unroll
    for (int i = 0; i < DD / 128; i++) {
        float4 v = row[lane + i * 32];
        s += v.x * v.x + v.y * v.y + v.z * v.z + v.w * v.w;
    }
#pragma unroll
    for (int o = 16; o; o >>= 1) s += __shfl_xor_sync(0xffffffffu, s, o);
    if (lane == 0) dst[r] = 1.f / fmaxf(sqrtf(s), 1e-8f);
}

// ---------------------------------------------------------------------------
// fp32 att SGEMM (proven R1): E = exp(cos sim)
// ---------------------------------------------------------------------------
__global__ __launch_bounds__(256)
void att_kernel(const float* __restrict__ P, const float* __restrict__ Q) {
    int b = blockIdx.z;
    const float* A = P + (size_t)b * LL * DD;
    const float* B = Q + (size_t)b * LL * DD;
    float* Eb = g_E + (size_t)b * LL * LL;
    const float* ip = g_invp + b * LL;
    const float* iq = g_invq + b * LL;
    int m0 = blockIdx.y * 128, n0 = blockIdx.x * 128;

    __shared__ float As[8][128];
    __shared__ float Bs[8][128];

    int t = threadIdx.x;
    int lm = t >> 1, lk = (t & 1) * 4;
    int tx = t & 15, ty = t >> 4;

    float acc[8][8];
#pragma unroll
    for (int i = 0; i < 8; i++)
#pragma unroll
        for (int j = 0; j < 8; j++) acc[i][j] = 0.f;

    const float* aptr = A + (size_t)(m0 + lm) * DD + lk;
    const float* bptr = B + (size_t)(n0 + lm) * DD + lk;

    for (int k0 = 0; k0 < DD; k0 += 8) {
        float4 av = *(const float4*)(aptr + k0);
        float4 bv = *(const float4*)(bptr + k0);
        __syncthreads();
        As[lk + 0][lm] = av.x; As[lk + 1][lm] = av.y;
        As[lk + 2][lm] = av.z; As[lk + 3][lm] = av.w;
        Bs[lk + 0][lm] = bv.x; Bs[lk + 1][lm] = bv.y;
        Bs[lk + 2][lm] = bv.z; Bs[lk + 3][lm] = bv.w;
        __syncthreads();
#pragma unroll
        for (int kk = 0; kk < 8; kk++) {
            float a[8], bb[8];
            *(float4*)&a[0]  = *(const float4*)&As[kk][ty * 4];
            *(float4*)&a[4]  = *(const float4*)&As[kk][64 + ty * 4];
            *(float4*)&bb[0] = *(const float4*)&Bs[kk][tx * 4];
            *(float4*)&bb[4] = *(const float4*)&Bs[kk][64 + tx * 4];
#pragma unroll
            for (int i = 0; i < 8; i++)
#pragma unroll
                for (int j = 0; j < 8; j++) acc[i][j] += a[i] * bb[j];
        }
    }
#pragma unroll
    for (int i = 0; i < 8; i++) {
        int m = m0 + ty * 4 + (i & 3) + (i >> 2) * 64;
        float rp = ip[m];
#pragma unroll
        for (int jg = 0; jg < 2; jg++) {
            int nb = n0 + tx * 4 + jg * 64;
            float4 v;
            v.x = __expf(acc[i][jg * 4 + 0] * rp * iq[nb + 0]);
            v.y = __expf(acc[i][jg * 4 + 1] * rp * iq[nb + 1]);
            v.z = __expf(acc[i][jg * 4 + 2] * rp * iq[nb + 2]);
            v.w = __expf(acc[i][jg * 4 + 3] * rp * iq[nb + 3]);
            *(float4*)&Eb[(size_t)m * LL + nb] = v;
        }
    }
}

// ---------------------------------------------------------------------------
// rowsum / colsum (proven R1, fp32)
// ---------------------------------------------------------------------------
__global__ void rowsum_kernel() {
    int warp = (blockIdx.x * blockDim.x + threadIdx.x) >> 5;
    int lane = threadIdx.x & 31;
    if (warp >= BB * LL) return;
    const float4* row = (const float4*)(g_E + (size_t)warp * LL);
    float s = 0.f;
#pragma unroll
    for (int i = 0; i < 4; i++) {
        float4 v = row[lane + i * 32];
        s += v.x + v.y + v.z + v.w;
    }
#pragma unroll
    for (int o = 16; o; o >>= 1) s += __shfl_xor_sync(0xffffffffu, s, o);
    if (lane == 0) g_rinv[warp] = 1.f / s;
}

__global__ void colsum_kernel() {
    int b = blockIdx.x;
    int j = threadIdx.x;
    const float* Eb = g_E + (size_t)b * LL * LL;
    float s0 = 0.f, s1 = 0.f, s2 = 0.f, s3 = 0.f;
    for (int i = 0; i < LL; i += 4) {
        s0 += Eb[(size_t)(i + 0) * LL + j];
        s1 += Eb[(size_t)(i + 1) * LL + j];
        s2 += Eb[(size_t)(i + 2) * LL + j];
        s3 += Eb[(size_t)(i + 3) * LL + j];
    }
    g_cinv[b * LL + j] = 1.f / (s0 + s1 + s2 + s3);
}

// ---------------------------------------------------------------------------
// fp32 out_p GEMM (proven R1 MODE 0): out_p = rinv[m] * E . q
// ---------------------------------------------------------------------------
__global__ __launch_bounds__(256)
void outp_kernel(const float* __restrict__ V, float* __restrict__ Out) {
    int b = blockIdx.z;
    const float* A = g_E + (size_t)b * LL * LL;
    const float* Bv = V + (size_t)b * LL * DD;
    float* Cb = Out + (size_t)b * LL * DD;
    int m0 = blockIdx.y * 128, n0 = blockIdx.x * 128;

    __shared__ float As[8][128];
    __shared__ float Bs[8][128];

    int t = threadIdx.x;
    int lm = t >> 1, lk = (t & 1) * 4;
    int bk = t >> 5, bn = (t & 31) * 4;
    int tx = t & 15, ty = t >> 4;

    float acc[8][8];
#pragma unroll
    for (int i = 0; i < 8; i++)
#pragma unroll
        for (int j = 0; j < 8; j++) acc[i][j] = 0.f;

    for (int k0 = 0; k0 < LL; k0 += 8) {
        float4 av = *(const float4*)(A + (size_t)(m0 + lm) * LL + k0 + lk);
        float4 bv = *(const float4*)(Bv + (size_t)(k0 + bk) * DD + n0 + bn);
        __syncthreads();
        As[lk + 0][lm] = av.x; As[lk + 1][lm] = av.y;
        As[lk + 2][lm] = av.z; As[lk + 3][lm] = av.w;
        *(float4*)&Bs[bk][bn] = bv;
        __syncthreads();
#pragma unroll
        for (int kk = 0; kk < 8; kk++) {
            float a[8], bb[8];
            *(float4*)&a[0]  = *(const float4*)&As[kk][ty * 4];
            *(float4*)&a[4]  = *(const float4*)&As[kk][64 + ty * 4];
            *(float4*)&bb[0] = *(const float4*)&Bs[kk][tx * 4];
            *(float4*)&bb[4] = *(const float4*)&Bs[kk][64 + tx * 4];
#pragma unroll
            for (int i = 0; i < 8; i++)
#pragma unroll
                for (int j = 0; j < 8; j++) acc[i][j] += a[i] * bb[j];
        }
    }
#pragma unroll
    for (int i = 0; i < 8; i++) {
        int m = m0 + ty * 4 + (i & 3) + (i >> 2) * 64;
        float rs = g_rinv[b * LL + m];
#pragma unroll
        for (int jg = 0; jg < 2; jg++) {
            int nb = n0 + tx * 4 + jg * 64;
            float4 v;
            v.x = acc[i][jg * 4 + 0] * rs;
            v.y = acc[i][jg * 4 + 1] * rs;
            v.z = acc[i][jg * 4 + 2] * rs;
            v.w = acc[i][jg * 4 + 3] * rs;
            *(float4*)&Cb[(size_t)m * DD + nb] = v;
        }
    }
}

// ---------------------------------------------------------------------------
// NEW: HMMA out_q. out_q[m,n] = sum_k (E[m,k]*cinv[k]) * p[k,n]
// BM=128, BN=64, BK=16, 2-stage cp.async, in-register bf16 split (3 mma/tile).
// A tile: fp32 [128][24] (rows padded 16->24 floats). B tile: fp32 [16][68].
// Fragments gathered by direct LDS (no ldmatrix). 256 thr = 8 warps (4m x 2n),
// warp tile 32x32.
// ---------------------------------------------------------------------------
#define ST_A 12288            // A tile bytes: 128*24*4
#define ST_SZ 16640           // + B tile 16*68*4 = 4352
#define CINV_OFF 33280        // after 2 stages

__global__ __launch_bounds__(256)
void outq_hmma_kernel(const float* __restrict__ P, float* __restrict__ Out) {
    __shared__ __align__(128) char smc[33536];   // 2*16640 + 2*64 cinv

    int b = blockIdx.z;
    int m0 = blockIdx.y * 128, n0 = blockIdx.x * 64;
    const float* E  = g_E + (size_t)b * LL * LL;
    const float* Pb = P + (size_t)b * LL * DD;
    const float* cv = g_cinv + b * LL;

    uint32_t sb = smem_u32(smc);
    int t = threadIdx.x, wid = t >> 5, lane = t & 31;
    int wm = (wid >> 1) * 32, wn = (wid & 1) * 32;
    int r4 = lane >> 2, c4 = lane & 3;

    float acc[2][4][4];
#pragma unroll
    for (int i = 0; i < 2; i++)
#pragma unroll
        for (int j = 0; j < 4; j++)
#pragma unroll
            for (int k = 0; k < 4; k++) acc[i][j][k] = 0.f;

    auto LOAD = [&](int st, int k0) {
        uint32_t base = sb + (uint32_t)st * ST_SZ;
        // A: 128 rows x 4 chunks(16B) = 512 chunks; 2 per thread
#pragma unroll
        for (int u = 0; u < 2; u++) {
            int c = t * 2 + u, row = c >> 2, cc = c & 3;
            CP_ASYNC(base + row * 96 + cc * 16,
                     E + (size_t)(m0 + row) * LL + k0 + cc * 4);
        }
        // B: 16 rows x 16 chunks = 256; 1 per thread
        {
            int row = t >> 4, cc = t & 15;
            CP_ASYNC(base + ST_A + row * 272 + cc * 16,
                     Pb + (size_t)(k0 + row) * DD + n0 + cc * 4);
        }
        if (t < 4)
            CP_ASYNC(sb + CINV_OFF + (uint32_t)st * 64 + t * 16, cv + k0 + t * 4);
    };

    LOAD(0, 0);
    CP_COMMIT();

    const int NIT = LL / 16;   // 32
    for (int it = 0; it < NIT; it++) {
        if (it + 1 < NIT) { LOAD((it + 1) & 1, (it + 1) * 16); CP_COMMIT(); CP_WAIT1(); }
        else              { CP_WAIT0(); }
        __syncthreads();

        const float* At = (const float*)(smc + (it & 1) * ST_SZ);           // [128][24]
        const float* Bt = (const float*)(smc + (it & 1) * ST_SZ + ST_A);    // [16][68]
        const float* Cs = (const float*)(smc + CINV_OFF + (it & 1) * 64);   // [16]

        float c0v = Cs[2 * c4], c1v = Cs[2 * c4 + 1];
        float c8v = Cs[2 * c4 + 8], c9v = Cs[2 * c4 + 9];

        uint32_t aHi[2][4], aLo[2][4], bHi[4][2], bLo[4][2];
#pragma unroll
        for (int i = 0; i < 2; i++) {
            int row0 = wm + i * 16 + r4;
            float2 p00 = *(const float2*)&At[row0 * 24 + 2 * c4];
            float2 p10 = *(const float2*)&At[(row0 + 8) * 24 + 2 * c4];
            float2 p01 = *(const float2*)&At[row0 * 24 + 2 * c4 + 8];
            float2 p11 = *(const float2*)&At[(row0 + 8) * 24 + 2 * c4 + 8];
            p00.x *= c0v; p00.y *= c1v; p10.x *= c0v; p10.y *= c1v;
            p01.x *= c8v; p01.y *= c9v; p11.x *= c8v; p11.y *= c9v;
            splitp(p00, aHi[i][0], aLo[i][0]);
            splitp(p10, aHi[i][1], aLo[i][1]);
            splitp(p01, aHi[i][2], aLo[i][2]);
            splitp(p11, aHi[i][3], aLo[i][3]);
        }
#pragma unroll
        for (int j = 0; j < 4; j++) {
            int n = wn + j * 8 + r4;
            float2 v0, v1;
            v0.x = Bt[(2 * c4) * 68 + n];
            v0.y = Bt[(2 * c4 + 1) * 68 + n];
            v1.x = Bt[(2 * c4 + 8) * 68 + n];
            v1.y = Bt[(2 * c4 + 9) * 68 + n];
            splitp(v0, bHi[j][0], bLo[j][0]);
            splitp(v1, bHi[j][1], bLo[j][1]);
        }
#pragma unroll
        for (int i = 0; i < 2; i++)
#pragma unroll
            for (int j = 0; j < 4; j++) {
                mma16816(acc[i][j], aHi[i], bHi[j]);
                mma16816(acc[i][j], aLo[i], bHi[j]);
                mma16816(acc[i][j], aHi[i], bLo[j]);
            }
        __syncthreads();
    }

    // Epilogue: c0,c1 at (row=l/4, col=2*(l%4)+{0,1}); c2,c3 at row+8.
#pragma unroll
    for (int i = 0; i < 2; i++)
#pragma unroll
        for (int half = 0; half < 2; half++) {
            int gi = m0 + wm + i * 16 + r4 + half * 8;
            size_t base = ((size_t)b * LL + gi) * DD;
#pragma unroll
            for (int j = 0; j < 4; j++) {
                int col = n0 + wn + j * 8 + c4 * 2;
                float2 v;
                v.x = acc[i][j][half * 2 + 0];
                v.y = acc[i][j][half * 2 + 1];
                *(float2*)(Out + base + col) = v;
            }
        }
}

// ---------------------------------------------------------------------------
extern "C" void kernel_launch(void* const* d_in, const int* in_sizes, int n_in,
                              void* d_out, int out_size) {
    const float* p = (const float*)d_in[0];
    const float* q = (const float*)d_in[1];
    float* out = (float*)d_out;
    float* out_p = out;
    float* out_q = out + (size_t)BB * LL * DD;

    norms_kernel<<<(2 * BB * LL) / 8, 256>>>(p, q);

    dim3 g_att(LL / 128, LL / 128, BB);
    att_kernel<<<g_att, 256>>>(p, q);

    rowsum_kernel<<<(BB * LL) / 8, 256>>>();
    colsum_kernel<<<BB, LL>>>();

    dim3 g_outp(DD / 128, LL / 128, BB);
    outp_kernel<<<g_outp, 256>>>(q, out_p);

    dim3 g_outq(DD / 64, LL / 128, BB);
    outq_hmma_kernel<<<g_outq, 256>>>(p, out_q);
}

// round 6
// speedup vs baseline: 1.6510x; 1.4437x over previous
#include <cuda_runtime.h>
#include <cuda_bf16.h>
#include <cstdint>
#include <math.h>

#define BB 64
#define LL 512
#define DD 768

// ---------------------------------------------------------------------------
// Scratch (device globals)
// ---------------------------------------------------------------------------
__device__ float g_E[(size_t)BB * LL * LL];   // exp(att), fp32
__device__ float g_invp[BB * LL];
__device__ float g_invq[BB * LL];
__device__ float g_rinv[BB * LL];
__device__ float g_cinv[BB * LL];

// ---------------------------------------------------------------------------
// Helpers
// ---------------------------------------------------------------------------
__device__ __forceinline__ uint32_t smem_u32(const void* p) {
    uint32_t a;
    asm("{ .reg .u64 t; cvta.to.shared.u64 t, %1; cvt.u32.u64 %0, t; }"
        : "=r"(a) : "l"(p));
    return a;
}
#define CP_ASYNC(dst, src) \
    asm volatile("cp.async.cg.shared.global [%0], [%1], 16;" :: "r"(dst), "l"(src))
#define CP_COMMIT() asm volatile("cp.async.commit_group;")
#define CP_WAIT1()  asm volatile("cp.async.wait_group 1;")
#define CP_WAIT0()  asm volatile("cp.async.wait_group 0;")

__device__ __forceinline__ void mma16816(float* c, const uint32_t* a, const uint32_t* b) {
    asm volatile("mma.sync.aligned.m16n8k16.row.col.f32.bf16.bf16.f32 "
                 "{%0,%1,%2,%3}, {%4,%5,%6,%7}, {%8,%9}, {%0,%1,%2,%3};"
                 : "+f"(c[0]), "+f"(c[1]), "+f"(c[2]), "+f"(c[3])
                 : "r"(a[0]), "r"(a[1]), "r"(a[2]), "r"(a[3]), "r"(b[0]), "r"(b[1]));
}
// split a float2 into packed bf16x2 hi and lo (x -> low 16 bits)
__device__ __forceinline__ void splitp(float2 v, uint32_t& hi, uint32_t& lo) {
    __nv_bfloat162 h = __floats2bfloat162_rn(v.x, v.y);
    hi = *(uint32_t*)&h;
    float hx = __bfloat162float(h.x);
    float hy = __bfloat162float(h.y);
    __nv_bfloat162 l = __floats2bfloat162_rn(v.x - hx, v.y - hy);
    lo = *(uint32_t*)&l;
}

// ---------------------------------------------------------------------------
// inverse L2 norms (proven R1)
// ---------------------------------------------------------------------------
__global__ void norms_kernel(const float* __restrict__ p,
                             const float* __restrict__ q) {
    int warp = (blockIdx.x * blockDim.x + threadIdx.x) >> 5;
    int lane = threadIdx.x & 31;
    if (warp >= 2 * BB * LL) return;
    const float* src; float* dst; int r;
    if (warp < BB * LL) { src = p; dst = g_invp; r = warp; }
    else                { src = q; dst = g_invq; r = warp - BB * LL; }
    const float4* row = (const float4*)(src + (size_t)r * DD);
    float s = 0.f;
#pragma unroll
    for (int i = 0; i < DD / 128; i++) {
        float4 v = row[lane + i * 32];
        s += v.x * v.x + v.y * v.y + v.z * v.z + v.w * v.w;
    }
#pragma unroll
    for (int o = 16; o; o >>= 1) s += __shfl_xor_sync(0xffffffffu, s, o);
    if (lane == 0) dst[r] = 1.f / fmaxf(sqrtf(s), 1e-8f);
}

// ---------------------------------------------------------------------------
// HMMA att: E[b,i,j] = exp( (p_i . q_j) * invp[i] * invq[j] )
// BM=128, BN=64, BK=16, 2-stage cp.async, in-register bf16 split.
// A tile [128][24] (rows of p, k-contig). B tile [64][24] (rows of q, k-contig).
// Stage = 128*96 + 64*96 = 18432 B; 2 stages = 36864 B static smem.
// 8 warps: 4(m) x 2(n), warp tile 32x32.
// ---------------------------------------------------------------------------
#define ATT_STG 18432
#define ATT_BOFF 12288

__global__ __launch_bounds__(256)
void att_hmma_kernel(const float* __restrict__ P, const float* __restrict__ Q) {
    __shared__ __align__(128) char smc[2 * ATT_STG];

    int b = blockIdx.z;
    int m0 = blockIdx.y * 128, n0 = blockIdx.x * 64;
    const float* A  = P + (size_t)b * LL * DD;
    const float* Bq = Q + (size_t)b * LL * DD;

    uint32_t sb = smem_u32(smc);
    int t = threadIdx.x, wid = t >> 5, lane = t & 31;
    int wm = (wid >> 1) * 32, wn = (wid & 1) * 32;
    int r4 = lane >> 2, c4 = lane & 3;

    float acc[2][4][4];
#pragma unroll
    for (int i = 0; i < 2; i++)
#pragma unroll
        for (int j = 0; j < 4; j++)
#pragma unroll
            for (int k = 0; k < 4; k++) acc[i][j][k] = 0.f;

    auto LOAD = [&](int st, int k0) {
        uint32_t base = sb + (uint32_t)st * ATT_STG;
        // A: 128 rows x 4 chunks(16B); 2 per thread
#pragma unroll
        for (int u = 0; u < 2; u++) {
            int c = t * 2 + u, row = c >> 2, cc = c & 3;
            CP_ASYNC(base + row * 96 + cc * 16,
                     A + (size_t)(m0 + row) * DD + k0 + cc * 4);
        }
        // B: 64 rows x 4 chunks = 256; 1 per thread
        {
            int row = t >> 2, cc = t & 3;
            CP_ASYNC(base + ATT_BOFF + row * 96 + cc * 16,
                     Bq + (size_t)(n0 + row) * DD + k0 + cc * 4);
        }
    };

    LOAD(0, 0);
    CP_COMMIT();

    const int NIT = DD / 16;   // 48
    for (int it = 0; it < NIT; it++) {
        if (it + 1 < NIT) { LOAD((it + 1) & 1, (it + 1) * 16); CP_COMMIT(); CP_WAIT1(); }
        else              { CP_WAIT0(); }
        __syncthreads();

        const float* At = (const float*)(smc + (it & 1) * ATT_STG);             // [128][24]
        const float* Bt = (const float*)(smc + (it & 1) * ATT_STG + ATT_BOFF);  // [64][24]

        uint32_t aHi[2][4], aLo[2][4], bHi[4][2], bLo[4][2];
#pragma unroll
        for (int i = 0; i < 2; i++) {
            int row0 = wm + i * 16 + r4;
            splitp(*(const float2*)&At[row0 * 24 + 2 * c4],       aHi[i][0], aLo[i][0]);
            splitp(*(const float2*)&At[(row0 + 8) * 24 + 2 * c4], aHi[i][1], aLo[i][1]);
            splitp(*(const float2*)&At[row0 * 24 + 2 * c4 + 8],   aHi[i][2], aLo[i][2]);
            splitp(*(const float2*)&At[(row0 + 8) * 24 + 2 * c4 + 8], aHi[i][3], aLo[i][3]);
        }
#pragma unroll
        for (int j = 0; j < 4; j++) {
            int n = wn + j * 8 + r4;
            splitp(*(const float2*)&Bt[n * 24 + 2 * c4],     bHi[j][0], bLo[j][0]);
            splitp(*(const float2*)&Bt[n * 24 + 2 * c4 + 8], bHi[j][1], bLo[j][1]);
        }
#pragma unroll
        for (int i = 0; i < 2; i++)
#pragma unroll
            for (int j = 0; j < 4; j++) {
                mma16816(acc[i][j], aHi[i], bHi[j]);
                mma16816(acc[i][j], aLo[i], bHi[j]);
                mma16816(acc[i][j], aHi[i], bLo[j]);
            }
        __syncthreads();
    }

    // Epilogue: cosine scale + exp -> g_E (fp32)
    const float* ip = g_invp + b * LL;
    const float* iq = g_invq + b * LL;
#pragma unroll
    for (int i = 0; i < 2; i++)
#pragma unroll
        for (int half = 0; half < 2; half++) {
            int gi = m0 + wm + i * 16 + r4 + half * 8;
            float rp = ip[gi];
            size_t base = ((size_t)b * LL + gi) * LL;
#pragma unroll
            for (int j = 0; j < 4; j++) {
                int col = n0 + wn + j * 8 + c4 * 2;
                float2 v;
                v.x = __expf(acc[i][j][half * 2 + 0] * rp * iq[col]);
                v.y = __expf(acc[i][j][half * 2 + 1] * rp * iq[col + 1]);
                *(float2*)(g_E + base + col) = v;
            }
        }
}

// ---------------------------------------------------------------------------
// rowsum / colsum (proven, fp32)
// ---------------------------------------------------------------------------
__global__ void rowsum_kernel() {
    int warp = (blockIdx.x * blockDim.x + threadIdx.x) >> 5;
    int lane = threadIdx.x & 31;
    if (warp >= BB * LL) return;
    const float4* row = (const float4*)(g_E + (size_t)warp * LL);
    float s = 0.f;
#pragma unroll
    for (int i = 0; i < 4; i++) {
        float4 v = row[lane + i * 32];
        s += v.x + v.y + v.z + v.w;
    }
#pragma unroll
    for (int o = 16; o; o >>= 1) s += __shfl_xor_sync(0xffffffffu, s, o);
    if (lane == 0) g_rinv[warp] = 1.f / s;
}

__global__ void colsum_kernel() {
    int b = blockIdx.x;
    int j = threadIdx.x;
    const float* Eb = g_E + (size_t)b * LL * LL;
    float s0 = 0.f, s1 = 0.f, s2 = 0.f, s3 = 0.f;
    for (int i = 0; i < LL; i += 4) {
        s0 += Eb[(size_t)(i + 0) * LL + j];
        s1 += Eb[(size_t)(i + 1) * LL + j];
        s2 += Eb[(size_t)(i + 2) * LL + j];
        s3 += Eb[(size_t)(i + 3) * LL + j];
    }
    g_cinv[b * LL + j] = 1.f / (s0 + s1 + s2 + s3);
}

// ---------------------------------------------------------------------------
// HMMA output GEMMs (proven R5 structure).
// MODE 1 (out_p): C[m,n] = rinv[m] * sum_k E[m,k] * q[k,n]
// MODE 2 (out_q): C[m,n] = sum_k (E[m,k]*cinv[k]) * p[k,n]
// BM=128, BN=64, BK=16. A tile [128][24] fp32; B tile [16][68] fp32.
// ---------------------------------------------------------------------------
#define ST_A 12288            // A tile bytes: 128*24*4
#define ST_SZ 16640           // + B tile 16*68*4 = 4352
#define CINV_OFF 33280        // after 2 stages

template <int MODE>
__global__ __launch_bounds__(256)
void out_hmma_kernel(const float* __restrict__ V, float* __restrict__ Out) {
    __shared__ __align__(128) char smc[33536];   // 2*16640 + 2*64 cinv

    int b = blockIdx.z;
    int m0 = blockIdx.y * 128, n0 = blockIdx.x * 64;
    const float* E  = g_E + (size_t)b * LL * LL;
    const float* Vb = V + (size_t)b * LL * DD;
    const float* cv = g_cinv + b * LL;

    uint32_t sb = smem_u32(smc);
    int t = threadIdx.x, wid = t >> 5, lane = t & 31;
    int wm = (wid >> 1) * 32, wn = (wid & 1) * 32;
    int r4 = lane >> 2, c4 = lane & 3;

    float acc[2][4][4];
#pragma unroll
    for (int i = 0; i < 2; i++)
#pragma unroll
        for (int j = 0; j < 4; j++)
#pragma unroll
            for (int k = 0; k < 4; k++) acc[i][j][k] = 0.f;

    auto LOAD = [&](int st, int k0) {
        uint32_t base = sb + (uint32_t)st * ST_SZ;
#pragma unroll
        for (int u = 0; u < 2; u++) {
            int c = t * 2 + u, row = c >> 2, cc = c & 3;
            CP_ASYNC(base + row * 96 + cc * 16,
                     E + (size_t)(m0 + row) * LL + k0 + cc * 4);
        }
        {
            int row = t >> 4, cc = t & 15;
            CP_ASYNC(base + ST_A + row * 272 + cc * 16,
                     Vb + (size_t)(k0 + row) * DD + n0 + cc * 4);
        }
        if (MODE == 2 && t < 4)
            CP_ASYNC(sb + CINV_OFF + (uint32_t)st * 64 + t * 16, cv + k0 + t * 4);
    };

    LOAD(0, 0);
    CP_COMMIT();

    const int NIT = LL / 16;   // 32
    for (int it = 0; it < NIT; it++) {
        if (it + 1 < NIT) { LOAD((it + 1) & 1, (it + 1) * 16); CP_COMMIT(); CP_WAIT1(); }
        else              { CP_WAIT0(); }
        __syncthreads();

        const float* At = (const float*)(smc + (it & 1) * ST_SZ);           // [128][24]
        const float* Bt = (const float*)(smc + (it & 1) * ST_SZ + ST_A);    // [16][68]

        float c0v = 1.f, c1v = 1.f, c8v = 1.f, c9v = 1.f;
        if (MODE == 2) {
            const float* Cs = (const float*)(smc + CINV_OFF + (it & 1) * 64);
            c0v = Cs[2 * c4];     c1v = Cs[2 * c4 + 1];
            c8v = Cs[2 * c4 + 8]; c9v = Cs[2 * c4 + 9];
        }

        uint32_t aHi[2][4], aLo[2][4], bHi[4][2], bLo[4][2];
#pragma unroll
        for (int i = 0; i < 2; i++) {
            int row0 = wm + i * 16 + r4;
            float2 p00 = *(const float2*)&At[row0 * 24 + 2 * c4];
            float2 p10 = *(const float2*)&At[(row0 + 8) * 24 + 2 * c4];
            float2 p01 = *(const float2*)&At[row0 * 24 + 2 * c4 + 8];
            float2 p11 = *(const float2*)&At[(row0 + 8) * 24 + 2 * c4 + 8];
            if (MODE == 2) {
                p00.x *= c0v; p00.y *= c1v; p10.x *= c0v; p10.y *= c1v;
                p01.x *= c8v; p01.y *= c9v; p11.x *= c8v; p11.y *= c9v;
            }
            splitp(p00, aHi[i][0], aLo[i][0]);
            splitp(p10, aHi[i][1], aLo[i][1]);
            splitp(p01, aHi[i][2], aLo[i][2]);
            splitp(p11, aHi[i][3], aLo[i][3]);
        }
#pragma unroll
        for (int j = 0; j < 4; j++) {
            int n = wn + j * 8 + r4;
            float2 v0, v1;
            v0.x = Bt[(2 * c4) * 68 + n];
            v0.y = Bt[(2 * c4 + 1) * 68 + n];
            v1.x = Bt[(2 * c4 + 8) * 68 + n];
            v1.y = Bt[(2 * c4 + 9) * 68 + n];
            splitp(v0, bHi[j][0], bLo[j][0]);
            splitp(v1, bHi[j][1], bLo[j][1]);
        }
#pragma unroll
        for (int i = 0; i < 2; i++)
#pragma unroll
            for (int j = 0; j < 4; j++) {
                mma16816(acc[i][j], aHi[i], bHi[j]);
                mma16816(acc[i][j], aLo[i], bHi[j]);
                mma16816(acc[i][j], aHi[i], bLo[j]);
            }
        __syncthreads();
    }

    // Epilogue
#pragma unroll
    for (int i = 0; i < 2; i++)
#pragma unroll
        for (int half = 0; half < 2; half++) {
            int gi = m0 + wm + i * 16 + r4 + half * 8;
            float rs = (MODE == 1) ? g_rinv[b * LL + gi] : 1.f;
            size_t base = ((size_t)b * LL + gi) * DD;
#pragma unroll
            for (int j = 0; j < 4; j++) {
                int col = n0 + wn + j * 8 + c4 * 2;
                float2 v;
                v.x = acc[i][j][half * 2 + 0] * rs;
                v.y = acc[i][j][half * 2 + 1] * rs;
                *(float2*)(Out + base + col) = v;
            }
        }
}

// ---------------------------------------------------------------------------
extern "C" void kernel_launch(void* const* d_in, const int* in_sizes, int n_in,
                              void* d_out, int out_size) {
    const float* p = (const float*)d_in[0];
    const float* q = (const float*)d_in[1];
    float* out = (float*)d_out;
    float* out_p = out;
    float* out_q = out + (size_t)BB * LL * DD;

    norms_kernel<<<(2 * BB * LL) / 8, 256>>>(p, q);

    att_hmma_kernel<<<dim3(LL / 64, LL / 128, BB), 256>>>(p, q);

    rowsum_kernel<<<(BB * LL) / 8, 256>>>();
    colsum_kernel<<<BB, LL>>>();

    out_hmma_kernel<1><<<dim3(DD / 64, LL / 128, BB), 256>>>(q, out_p);
    out_hmma_kernel<2><<<dim3(DD / 64, LL / 128, BB), 256>>>(p, out_q);
}

// round 8
// speedup vs baseline: 1.8186x; 1.1015x over previous
#include <cuda_runtime.h>
#include <cuda_bf16.h>
#include <cstdint>
#include <math.h>

#define BB 64
#define LL 512
#define DD 768

// ---------------------------------------------------------------------------
// Scratch (device globals)
// ---------------------------------------------------------------------------
__device__ float g_E[(size_t)BB * LL * LL];   // exp(att), fp32
__device__ float g_invp[BB * LL];
__device__ float g_invq[BB * LL];
__device__ float g_rinv[BB * LL];
__device__ float g_cinv[BB * LL];

// ---------------------------------------------------------------------------
// Helpers
// ---------------------------------------------------------------------------
__device__ __forceinline__ uint32_t smem_u32(const void* p) {
    uint32_t a;
    asm("{ .reg .u64 t; cvta.to.shared.u64 t, %1; cvt.u32.u64 %0, t; }"
        : "=r"(a) : "l"(p));
    return a;
}
#define CP_ASYNC(dst, src) \
    asm volatile("cp.async.cg.shared.global [%0], [%1], 16;" :: "r"(dst), "l"(src))
#define CP_COMMIT() asm volatile("cp.async.commit_group;")
#define CP_WAIT1()  asm volatile("cp.async.wait_group 1;")
#define CP_WAIT0()  asm volatile("cp.async.wait_group 0;")

__device__ __forceinline__ void mma16816(float* c, const uint32_t* a, const uint32_t* b) {
    asm volatile("mma.sync.aligned.m16n8k16.row.col.f32.bf16.bf16.f32 "
                 "{%0,%1,%2,%3}, {%4,%5,%6,%7}, {%8,%9}, {%0,%1,%2,%3};"
                 : "+f"(c[0]), "+f"(c[1]), "+f"(c[2]), "+f"(c[3])
                 : "r"(a[0]), "r"(a[1]), "r"(a[2]), "r"(a[3]), "r"(b[0]), "r"(b[1]));
}
// split a float2 into packed bf16x2 hi and lo (x -> low 16 bits)
__device__ __forceinline__ void splitp(float2 v, uint32_t& hi, uint32_t& lo) {
    __nv_bfloat162 h = __floats2bfloat162_rn(v.x, v.y);
    hi = *(uint32_t*)&h;
    float hx = __bfloat162float(h.x);
    float hy = __bfloat162float(h.y);
    __nv_bfloat162 l = __floats2bfloat162_rn(v.x - hx, v.y - hy);
    lo = *(uint32_t*)&l;
}
// hi-only pack
__device__ __forceinline__ uint32_t packbf(float2 v) {
    __nv_bfloat162 h = __floats2bfloat162_rn(v.x, v.y);
    return *(uint32_t*)&h;
}

// ---------------------------------------------------------------------------
// inverse L2 norms (proven R1)
// ---------------------------------------------------------------------------
__global__ void norms_kernel(const float* __restrict__ p,
                             const float* __restrict__ q) {
    int warp = (blockIdx.x * blockDim.x + threadIdx.x) >> 5;
    int lane = threadIdx.x & 31;
    if (warp >= 2 * BB * LL) return;
    const float* src; float* dst; int r;
    if (warp < BB * LL) { src = p; dst = g_invp; r = warp; }
    else                { src = q; dst = g_invq; r = warp - BB * LL; }
    const float4* row = (const float4*)(src + (size_t)r * DD);
    float s = 0.f;
#pragma unroll
    for (int i = 0; i < DD / 128; i++) {
        float4 v = row[lane + i * 32];
        s += v.x * v.x + v.y * v.y + v.z * v.z + v.w * v.w;
    }
#pragma unroll
    for (int o = 16; o; o >>= 1) s += __shfl_xor_sync(0xffffffffu, s, o);
    if (lane == 0) dst[r] = 1.f / fmaxf(sqrtf(s), 1e-8f);
}

// ---------------------------------------------------------------------------
// HMMA att (hi-only bf16): E[b,i,j] = exp( (p_i . q_j) * invp[i] * invq[j] )
// BM=128, BN=64, BK=16, 2-stage cp.async. fp32 tiles, cvt-only fragments,
// 8 MMAs per k16 step. Cosine error ~7e-5 absolute (random-sign cancellation).
// ---------------------------------------------------------------------------
#define ATT_STG 18432
#define ATT_BOFF 12288

__global__ __launch_bounds__(256)
void att_hmma_kernel(const float* __restrict__ P, const float* __restrict__ Q) {
    __shared__ __align__(128) char smc[2 * ATT_STG];

    int b = blockIdx.z;
    int m0 = blockIdx.y * 128, n0 = blockIdx.x * 64;
    const float* A  = P + (size_t)b * LL * DD;
    const float* Bq = Q + (size_t)b * LL * DD;

    uint32_t sb = smem_u32(smc);
    int t = threadIdx.x, wid = t >> 5, lane = t & 31;
    int wm = (wid >> 1) * 32, wn = (wid & 1) * 32;
    int r4 = lane >> 2, c4 = lane & 3;

    float acc[2][4][4];
#pragma unroll
    for (int i = 0; i < 2; i++)
#pragma unroll
        for (int j = 0; j < 4; j++)
#pragma unroll
            for (int k = 0; k < 4; k++) acc[i][j][k] = 0.f;

    auto LOAD = [&](int st, int k0) {
        uint32_t base = sb + (uint32_t)st * ATT_STG;
#pragma unroll
        for (int u = 0; u < 2; u++) {
            int c = t * 2 + u, row = c >> 2, cc = c & 3;
            CP_ASYNC(base + row * 96 + cc * 16,
                     A + (size_t)(m0 + row) * DD + k0 + cc * 4);
        }
        {
            int row = t >> 2, cc = t & 3;
            CP_ASYNC(base + ATT_BOFF + row * 96 + cc * 16,
                     Bq + (size_t)(n0 + row) * DD + k0 + cc * 4);
        }
    };

    LOAD(0, 0);
    CP_COMMIT();

    const int NIT = DD / 16;   // 48
    for (int it = 0; it < NIT; it++) {
        if (it + 1 < NIT) { LOAD((it + 1) & 1, (it + 1) * 16); CP_COMMIT(); CP_WAIT1(); }
        else              { CP_WAIT0(); }
        __syncthreads();

        const float* At = (const float*)(smc + (it & 1) * ATT_STG);             // [128][24]
        const float* Bt = (const float*)(smc + (it & 1) * ATT_STG + ATT_BOFF);  // [64][24]

        uint32_t aHi[2][4], bHi[4][2];
#pragma unroll
        for (int i = 0; i < 2; i++) {
            int row0 = wm + i * 16 + r4;
            aHi[i][0] = packbf(*(const float2*)&At[row0 * 24 + 2 * c4]);
            aHi[i][1] = packbf(*(const float2*)&At[(row0 + 8) * 24 + 2 * c4]);
            aHi[i][2] = packbf(*(const float2*)&At[row0 * 24 + 2 * c4 + 8]);
            aHi[i][3] = packbf(*(const float2*)&At[(row0 + 8) * 24 + 2 * c4 + 8]);
        }
#pragma unroll
        for (int j = 0; j < 4; j++) {
            int n = wn + j * 8 + r4;
            bHi[j][0] = packbf(*(const float2*)&Bt[n * 24 + 2 * c4]);
            bHi[j][1] = packbf(*(const float2*)&Bt[n * 24 + 2 * c4 + 8]);
        }
#pragma unroll
        for (int i = 0; i < 2; i++)
#pragma unroll
            for (int j = 0; j < 4; j++)
                mma16816(acc[i][j], aHi[i], bHi[j]);
        __syncthreads();
    }

    // Epilogue: cosine scale + exp -> g_E (fp32)
    const float* ip = g_invp + b * LL;
    const float* iq = g_invq + b * LL;
#pragma unroll
    for (int i = 0; i < 2; i++)
#pragma unroll
        for (int half = 0; half < 2; half++) {
            int gi = m0 + wm + i * 16 + r4 + half * 8;
            float rp = ip[gi];
            size_t base = ((size_t)b * LL + gi) * LL;
#pragma unroll
            for (int j = 0; j < 4; j++) {
                int col = n0 + wn + j * 8 + c4 * 2;
                float2 v;
                v.x = __expf(acc[i][j][half * 2 + 0] * rp * iq[col]);
                v.y = __expf(acc[i][j][half * 2 + 1] * rp * iq[col + 1]);
                *(float2*)(g_E + base + col) = v;
            }
        }
}

// ---------------------------------------------------------------------------
// rowsum / colsum (proven, fp32)
// ---------------------------------------------------------------------------
__global__ void rowsum_kernel() {
    int warp = (blockIdx.x * blockDim.x + threadIdx.x) >> 5;
    int lane = threadIdx.x & 31;
    if (warp >= BB * LL) return;
    const float4* row = (const float4*)(g_E + (size_t)warp * LL);
    float s = 0.f;
#pragma unroll
    for (int i = 0; i < 4; i++) {
        float4 v = row[lane + i * 32];
        s += v.x + v.y + v.z + v.w;
    }
#pragma unroll
    for (int o = 16; o; o >>= 1) s += __shfl_xor_sync(0xffffffffu, s, o);
    if (lane == 0) g_rinv[warp] = 1.f / s;
}

__global__ void colsum_kernel() {
    int b = blockIdx.x;
    int j = threadIdx.x;
    const float* Eb = g_E + (size_t)b * LL * LL;
    float s0 = 0.f, s1 = 0.f, s2 = 0.f, s3 = 0.f;
    for (int i = 0; i < LL; i += 4) {
        s0 += Eb[(size_t)(i + 0) * LL + j];
        s1 += Eb[(size_t)(i + 1) * LL + j];
        s2 += Eb[(size_t)(i + 2) * LL + j];
        s3 += Eb[(size_t)(i + 3) * LL + j];
    }
    g_cinv[b * LL + j] = 1.f / (s0 + s1 + s2 + s3);
}

// ---------------------------------------------------------------------------
// HMMA output GEMMs (proven R5/R6 structure, 3-MMA split kept).
// MODE 1 (out_p): C[m,n] = rinv[m] * sum_k E[m,k] * q[k,n]
// MODE 2 (out_q): C[m,n] = sum_k (E[m,k]*cinv[k]) * p[k,n]
// ---------------------------------------------------------------------------
#define ST_A 12288            // A tile bytes: 128*24*4
#define ST_SZ 16640           // + B tile 16*68*4 = 4352
#define CINV_OFF 33280        // after 2 stages

template <int MODE>
__global__ __launch_bounds__(256)
void out_hmma_kernel(const float* __restrict__ V, float* __restrict__ Out) {
    __shared__ __align__(128) char smc[33536];   // 2*16640 + 2*64 cinv

    int b = blockIdx.z;
    int m0 = blockIdx.y * 128, n0 = blockIdx.x * 64;
    const float* E  = g_E + (size_t)b * LL * LL;
    const float* Vb = V + (size_t)b * LL * DD;
    const float* cv = g_cinv + b * LL;

    uint32_t sb = smem_u32(smc);
    int t = threadIdx.x, wid = t >> 5, lane = t & 31;
    int wm = (wid >> 1) * 32, wn = (wid & 1) * 32;
    int r4 = lane >> 2, c4 = lane & 3;

    float acc[2][4][4];
#pragma unroll
    for (int i = 0; i < 2; i++)
#pragma unroll
        for (int j = 0; j < 4; j++)
#pragma unroll
            for (int k = 0; k < 4; k++) acc[i][j][k] = 0.f;

    auto LOAD = [&](int st, int k0) {
        uint32_t base = sb + (uint32_t)st * ST_SZ;
#pragma unroll
        for (int u = 0; u < 2; u++) {
            int c = t * 2 + u, row = c >> 2, cc = c & 3;
            CP_ASYNC(base + row * 96 + cc * 16,
                     E + (size_t)(m0 + row) * LL + k0 + cc * 4);
        }
        {
            int row = t >> 4, cc = t & 15;
            CP_ASYNC(base + ST_A + row * 272 + cc * 16,
                     Vb + (size_t)(k0 + row) * DD + n0 + cc * 4);
        }
        if (MODE == 2 && t < 4)
            CP_ASYNC(sb + CINV_OFF + (uint32_t)st * 64 + t * 16, cv + k0 + t * 4);
    };

    LOAD(0, 0);
    CP_COMMIT();

    const int NIT = LL / 16;   // 32
    for (int it = 0; it < NIT; it++) {
        if (it + 1 < NIT) { LOAD((it + 1) & 1, (it + 1) * 16); CP_COMMIT(); CP_WAIT1(); }
        else              { CP_WAIT0(); }
        __syncthreads();

        const float* At = (const float*)(smc + (it & 1) * ST_SZ);           // [128][24]
        const float* Bt = (const float*)(smc + (it & 1) * ST_SZ + ST_A);    // [16][68]

        float c0v = 1.f, c1v = 1.f, c8v = 1.f, c9v = 1.f;
        if (MODE == 2) {
            const float* Cs = (const float*)(smc + CINV_OFF + (it & 1) * 64);
            c0v = Cs[2 * c4];     c1v = Cs[2 * c4 + 1];
            c8v = Cs[2 * c4 + 8]; c9v = Cs[2 * c4 + 9];
        }

        uint32_t aHi[2][4], aLo[2][4], bHi[4][2], bLo[4][2];
#pragma unroll
        for (int i = 0; i < 2; i++) {
            int row0 = wm + i * 16 + r4;
            float2 p00 = *(const float2*)&At[row0 * 24 + 2 * c4];
            float2 p10 = *(const float2*)&At[(row0 + 8) * 24 + 2 * c4];
            float2 p01 = *(const float2*)&At[row0 * 24 + 2 * c4 + 8];
            float2 p11 = *(const float2*)&At[(row0 + 8) * 24 + 2 * c4 + 8];
            splitp(p00, aHi[i][0], aLo[i][0]);
            splitp(p10, aHi[i][1], aLo[i][1]);
            splitp(p01, aHi[i][2], aLo[i][2]);
            splitp(p11, aHi[i][3], aLo[i][3]);
        }
#pragma unroll
        for (int j = 0; j < 4; j++) {
            int n = wn + j * 8 + r4;
            float2 v0, v1;
            v0.x = Bt[(2 * c4) * 68 + n];
            v0.y = Bt[(2 * c4 + 1) * 68 + n];
            v1.x = Bt[(2 * c4 + 8) * 68 + n];
            v1.y = Bt[(2 * c4 + 9) * 68 + n];
            if (MODE == 2) {
                v0.x *= c0v; v0.y *= c1v;
                v1.x *= c8v; v1.y *= c9v;
            }
            splitp(v0, bHi[j][0], bLo[j][0]);
            splitp(v1, bHi[j][1], bLo[j][1]);
        }
#pragma unroll
        for (int i = 0; i < 2; i++)
#pragma unroll
            for (int j = 0; j < 4; j++) {
                mma16816(acc[i][j], aHi[i], bHi[j]);
                mma16816(acc[i][j], aLo[i], bHi[j]);
                mma16816(acc[i][j], aHi[i], bLo[j]);
            }
        __syncthreads();
    }

    // Epilogue
#pragma unroll
    for (int i = 0; i < 2; i++)
#pragma unroll
        for (int half = 0; half < 2; half++) {
            int gi = m0 + wm + i * 16 + r4 + half * 8;
            float rs = (MODE == 1) ? g_rinv[b * LL + gi] : 1.f;
            size_t base = ((size_t)b * LL + gi) * DD;
#pragma unroll
            for (int j = 0; j < 4; j++) {
                int col = n0 + wn + j * 8 + c4 * 2;
                float2 v;
                v.x = acc[i][j][half * 2 + 0] * rs;
                v.y = acc[i][j][half * 2 + 1] * rs;
                *(float2*)(Out + base + col) = v;
            }
        }
}

// ---------------------------------------------------------------------------
extern "C" void kernel_launch(void* const* d_in, const int* in_sizes, int n_in,
                              void* d_out, int out_size) {
    const float* p = (const float*)d_in[0];
    const float* q = (const float*)d_in[1];
    float* out = (float*)d_out;
    float* out_p = out;
    float* out_q = out + (size_t)BB * LL * DD;

    norms_kernel<<<(2 * BB * LL) / 8, 256>>>(p, q);

    att_hmma_kernel<<<dim3(LL / 64, LL / 128, BB), 256>>>(p, q);

    rowsum_kernel<<<(BB * LL) / 8, 256>>>();
    colsum_kernel<<<BB, LL>>>();

    out_hmma_kernel<1><<<dim3(DD / 64, LL / 128, BB), 256>>>(q, out_p);
    out_hmma_kernel<2><<<dim3(DD / 64, LL / 128, BB), 256>>>(p, out_q);
}